// round 3
// baseline (speedup 1.0000x reference)
#include <cuda_runtime.h>
#include <cstdint>

#define BB 1024
#define TT 256
#define NN 64

// Packed transition matrix: g_P[j*32 + l] = pack(P[j][l], P[j][l+32])
__device__ unsigned long long g_P[64 * 32];
__device__ float g_Ps[NN];      // exp(strans - lse(strans))
__device__ float g_Pe[NN];      // exp(etrans - lse(etrans))
__device__ int   g_mask_dtype;  // 0 = uint8/bool, 1 = int32, 2 = float32
__device__ float g_logZ[BB];

__device__ __forceinline__ unsigned long long pack2(float lo, float hi) {
    return ((unsigned long long)__float_as_uint(hi) << 32) |
           (unsigned long long)__float_as_uint(lo);
}

__device__ __forceinline__ float warp_max(float v) {
#pragma unroll
    for (int o = 16; o; o >>= 1) v = fmaxf(v, __shfl_xor_sync(0xffffffffu, v, o));
    return v;
}
__device__ __forceinline__ float warp_sum(float v) {
#pragma unroll
    for (int o = 16; o; o >>= 1) v += __shfl_xor_sync(0xffffffffu, v, o);
    return v;
}
__device__ __forceinline__ int warp_sum_i(int v) {
#pragma unroll
    for (int o = 16; o; o >>= 1) v += __shfl_xor_sync(0xffffffffu, v, o);
    return v;
}

// ---------------------------------------------------------------------------
// Prep: fully parallel. grid=64, block=64.
//   warp0 of block j : normalize trans row j
//   warp1 of block 0 : strans;  block 1 : etrans;  block 2 : mask dtype detect
// ---------------------------------------------------------------------------
__global__ void prep_kernel(const float* __restrict__ trans,
                            const float* __restrict__ strans,
                            const float* __restrict__ etrans,
                            const void*  __restrict__ mask)
{
    const int j    = blockIdx.x;
    const int w    = threadIdx.x >> 5;
    const int lane = threadIdx.x & 31;

    if (w == 0) {
        // Row-normalized transition probabilities: P[j][k] = exp(trans_n[j][k])
        float a = trans[j * NN + lane];
        float b = trans[j * NN + lane + 32];
        float mx = warp_max(fmaxf(a, b));
        float ea = __expf(a - mx), eb = __expf(b - mx);
        float inv = __fdividef(1.f, warp_sum(ea + eb));
        g_P[j * 32 + lane] = pack2(ea * inv, eb * inv);
    } else if (j == 0) {
        float a = strans[lane], b = strans[lane + 32];
        float mx = warp_max(fmaxf(a, b));
        float ea = __expf(a - mx), eb = __expf(b - mx);
        float inv = __fdividef(1.f, warp_sum(ea + eb));
        g_Ps[lane] = ea * inv;  g_Ps[lane + 32] = eb * inv;
    } else if (j == 1) {
        float a = etrans[lane], b = etrans[lane + 32];
        float mx = warp_max(fmaxf(a, b));
        float ea = __expf(a - mx), eb = __expf(b - mx);
        float inv = __fdividef(1.f, warp_sum(ea + eb));
        g_Pe[lane] = ea * inv;  g_Pe[lane + 32] = eb * inv;
    } else if (j == 2) {
        // mask dtype detection on row 0: lens >= T/2, so row-0 true count in
        // [128,256] (prefix mask).
        const unsigned* mu = (const unsigned*)mask;   // first 256 bytes
        int s8 = warp_sum_i(__popc(mu[lane]) + __popc(mu[lane + 32]));
        int dt;
        if (s8 >= 128 && s8 <= 256) {
            dt = 0;                                    // 1-byte bool (0/1 bytes)
        } else {
            const int* mi = (const int*)mask;          // first 256 ints in-bounds
            long long s = 0;
            for (int i = lane; i < 256; i += 32) s += mi[i];
#pragma unroll
            for (int o = 16; o; o >>= 1) s += __shfl_xor_sync(0xffffffffu, s, o);
            dt = (s >= 128 && s <= 256) ? 1 : 2;       // int32 vs float32
        }
        if (lane == 0) g_mask_dtype = dt;
    }
}

// ---------------------------------------------------------------------------
// Main: warp-per-batch exp-domain forward recursion.
// Lane l owns labels {l, l+32}. P held in 128 registers as f32x2 pairs.
// Emit is prefetched 4 steps ahead through a register ring (MLP=8 per warp,
// ~520 cyc of coverage > DRAM latency), so the per-step critical path is the
// LDS.128 broadcast + 16-deep packed-FMA chains only.
// ---------------------------------------------------------------------------
#define FMA2(acc, a, b) \
    asm("fma.rn.f32x2 %0, %1, %2, %0;" : "+l"(acc) : "l"(a), "l"(b))
#define ADD2(acc, a) \
    asm("add.rn.f32x2 %0, %0, %1;" : "+l"(acc) : "l"(a))

__global__ void __launch_bounds__(128, 2)
crf_kernel(const float* __restrict__ emit, const void* __restrict__ mask)
{
    const int lane = threadIdx.x & 31;
    const int wib  = threadIdx.x >> 5;              // warp in block (0..3)
    const int b    = blockIdx.x * 4 + wib;          // batch index (0..1023)

    // Load P into registers (coalesced, L2-resident: 16KB total)
    unsigned long long p[64];
#pragma unroll
    for (int j = 0; j < 64; j++) p[j] = g_P[j * 32 + lane];

    // Sequence length from monotone mask
    const int dt = g_mask_dtype;
    int len = 0;
    if (dt == 0) {
        const unsigned* m = (const unsigned*)mask;  // bytes are exactly 0x00/0x01
        len = __popc(m[b * 64 + lane]) + __popc(m[b * 64 + 32 + lane]);
    } else if (dt == 1) {
        const int* m = (const int*)mask + (size_t)b * TT;
        for (int t = lane; t < TT; t += 32) len += (m[t] != 0);
    } else {
        const float* m = (const float*)mask + (size_t)b * TT;
        for (int t = lane; t < TT; t += 32) len += (m[t] != 0.f);
    }
    len = warp_sum_i(len);

    const float* eb = emit + (size_t)b * TT * NN;

    // alpha0 = strans_n + emit[0]  ->  A0 = Ps * exp(emit0)
    float ax = g_Ps[lane]      * __expf(eb[lane]);
    float ay = g_Ps[lane + 32] * __expf(eb[lane + 32]);
    float C  = 0.f;

    // Broadcast buffer: duplicated pairs (a_j, a_j), 16B-aligned so the inner
    // loop reads two pairs per LDS.128. Double-buffered: one syncwarp/step.
    __shared__ alignas(16) unsigned long long sh[4][2][64];

    // 4-deep raw emit prefetch ring for steps t..t+3
    float rxv[4], ryv[4];
#pragma unroll
    for (int u = 0; u < 4; u++) {
        int idx = 1 + u; if (idx > len - 1) idx = len - 1;
        rxv[u] = eb[idx * NN + lane];
        ryv[u] = eb[idx * NN + lane + 32];
    }

    for (int t = 1; t < len; t += 4) {
#pragma unroll
        for (int u = 0; u < 4; u++) {
            const int tt  = t + u;
            const int buf = tt & 1;
            sh[wib][buf][lane]      = pack2(ax, ax);
            sh[wib][buf][lane + 32] = pack2(ay, ay);

            // exp of current step (MUFU latency hidden under FMA chain)
            const float exe = __expf(rxv[u]);
            const float eye = __expf(ryv[u]);
            // refill ring slot with step tt+4 (distance-4 prefetch)
            int tp = tt + 4; if (tp > len - 1) tp = len - 1;
            rxv[u] = eb[tp * NN + lane];
            ryv[u] = eb[tp * NN + lane + 32];

            __syncwarp();

            const ulonglong2* sa = (const ulonglong2*)sh[wib][buf];
            unsigned long long acc0 = 0ull, acc1 = 0ull, acc2 = 0ull, acc3 = 0ull;
#pragma unroll
            for (int i = 0; i < 16; i++) {
                ulonglong2 v0 = sa[2 * i];       // pairs j=4i, 4i+1
                ulonglong2 v1 = sa[2 * i + 1];   // pairs j=4i+2, 4i+3
                FMA2(acc0, v0.x, p[4 * i]);
                FMA2(acc1, v0.y, p[4 * i + 1]);
                FMA2(acc2, v1.x, p[4 * i + 2]);
                FMA2(acc3, v1.y, p[4 * i + 3]);
            }
            ADD2(acc0, acc1);
            ADD2(acc2, acc3);
            ADD2(acc0, acc2);
            const float sx = __uint_as_float((unsigned)acc0);
            const float sy = __uint_as_float((unsigned)(acc0 >> 32));

            if (tt < len) {
                ax = sx * exe;
                ay = sy * eye;
                // Renormalize every 8 steps: growth e^{8*max|emit|} << FLT_MAX
                if ((tt & 7) == 0) {
                    float s = warp_sum(ax + ay);
                    C += __logf(s);
                    float inv = __fdividef(1.f, s);
                    ax *= inv;
                    ay *= inv;
                }
            }
        }
    }

    // logZ_b = C + log(sum_k A_k * exp(etrans_n_k))
    float z = warp_sum(ax * g_Pe[lane] + ay * g_Pe[lane + 32]);
    if (lane == 0) g_logZ[b] = C + __logf(z);
}

// ---------------------------------------------------------------------------
// Deterministic batch reduction (no float atomics).
// ---------------------------------------------------------------------------
__global__ void reduce_kernel(float* __restrict__ out)
{
    __shared__ float s[256];
    int tid = threadIdx.x;
    float v = 0.f;
    for (int i = tid; i < BB; i += 256) v += g_logZ[i];
    s[tid] = v;
    __syncthreads();
    for (int o = 128; o; o >>= 1) {
        if (tid < o) s[tid] += s[tid + o];
        __syncthreads();
    }
    if (tid == 0) out[0] = s[0];
}

extern "C" void kernel_launch(void* const* d_in, const int* in_sizes, int n_in,
                              void* d_out, int out_size)
{
    // Resolve inputs by size (defensive), keeping dict order for the two
    // size-64 vectors (strans before etrans).
    const float* emit   = nullptr;
    const float* trans  = nullptr;
    const float* strans = nullptr;
    const float* etrans = nullptr;
    const void*  mask   = nullptr;
    for (int i = 0; i < n_in; i++) {
        long long sz = in_sizes[i];
        if (sz == (long long)BB * TT * NN)      emit  = (const float*)d_in[i];
        else if (sz == NN * NN)                 trans = (const float*)d_in[i];
        else if (sz == (long long)BB * TT)      mask  = d_in[i];
        else if (sz == NN) {
            if (!strans) strans = (const float*)d_in[i];
            else         etrans = (const float*)d_in[i];
        }
    }

    prep_kernel<<<64, 64>>>(trans, strans, etrans, mask);
    crf_kernel<<<256, 128>>>(emit, mask);
    reduce_kernel<<<1, 256>>>((float*)d_out);
}